// round 8
// baseline (speedup 1.0000x reference)
#include <cuda_runtime.h>

// SpatialTransformer: 1-D bilinear warp along W.
//
// R6 structure (proven: 32 regs, occ ~80%): flat mapping, 4 channels per
// thread, coefficients computed once per thread (fb[4] only in fast path).
// Fast path (runtime-verified, never assumed): floor(w+d)==w and interior
// group -> lerp va + fb*(vb-va), one LDG.128 + one LDG.32 per channel.
// Fallback = exact reference formula with row-relative indexing.
//
// R8 change: ASYMMETRIC cache policy. Measured DRAM traffic (216 MB) is
// below nominal (270 MB) -> cross-replay L2 residency is real. So:
//   input  -> __ldcs (evict-first: read once, don't evict output lines)
//   output -> default write-back (keep dirty lines resident across replays)
//   disparity -> default (2 MB, reused 16x per iteration)

#define ST_B 4
#define ST_C 64
#define ST_H 256
#define ST_W 512

constexpr int HW      = ST_H * ST_W;        // 131072
constexpr int NC      = 4;                  // channels per thread
constexpr int THREADS = 256;
constexpr int NTHREADS = ST_B * (ST_C / NC) * ST_H * (ST_W / 4);  // 2,097,152

__global__ void __launch_bounds__(THREADS)
spatial_transformer_c4a_kernel(const float* __restrict__ in,
                               const float* __restrict__ disp,
                               float* __restrict__ out)
{
    const int g  = blockIdx.x * blockDim.x + threadIdx.x;
    const int gw = g & 127;            // w-group (lanes -> consecutive: coalesced)
    const int h  = (g >> 7) & 255;
    const int cg = (g >> 15) & 15;
    const int b  = g >> 19;
    const int w0 = gw << 2;

    // disparity (b, h, w0..w0+3): 2 MB, reused 16x -> default (L2-resident)
    const float4 d4 = *(const float4*)(disp + ((((b << 8) | h) << 9) | w0));
    const float dv[4] = {d4.x, d4.y, d4.z, d4.w};

    float fb[4];
    bool  fast = (gw <= 126);          // need w0+4 < W for the fast path
    #pragma unroll
    for (int j = 0; j < 4; ++j) {
        float wj = (float)(w0 + j);
        float ry = wj + dv[j];
        float ra = floorf(ry);
        fb[j] = ry - ra;
        fast  = fast && (ra == wj);    // identity pair + in-bounds
    }

    const int c0   = cg << 2;
    const size_t base = ((size_t)((((b << 6) | c0) << 8) | h) << 9) + w0;
    const float* row  = in  + base;    // points at w0 within the row
    float*       orow = out + base;

    if (fast) {
        float4 v[NC];
        float  vn[NC];
        #pragma unroll
        for (int i = 0; i < NC; ++i) {          // front-batched: MLP = 8
            v[i]  = __ldcs((const float4*)(row + i * HW));   // streaming read
            vn[i] = __ldcs(row + i * HW + 4);
        }
        #pragma unroll
        for (int i = 0; i < NC; ++i) {
            float4 o;
            o.x = fmaf(fb[0], v[i].y - v[i].x, v[i].x);
            o.y = fmaf(fb[1], v[i].z - v[i].y, v[i].y);
            o.z = fmaf(fb[2], v[i].w - v[i].z, v[i].z);
            o.w = fmaf(fb[3], vn[i]  - v[i].w, v[i].w);
            *(float4*)(orow + i * HW) = o;      // default write-back
        }
    } else {
        // exact reference formula (clamped gather + oob zeroing)
        float wa[4], wb[4];
        int   ia[4], ib[4];
        #pragma unroll
        for (int j = 0; j < 4; ++j) {
            int   w  = w0 + j;
            float ry = (float)w + dv[j];
            float ra = floorf(ry);
            float f  = ry - ra;
            int   a  = (int)ra;
            ia[j] = min(max(a,     0), ST_W - 1);
            ib[j] = min(max(a + 1, 0), ST_W - 1);
            float sc = (ry < 0.0f || ry > (float)(ST_W - 1)) ? 0.0f : 1.0f;
            wa[j] = (1.0f - f) * sc;
            wb[j] = f * sc;
        }
        #pragma unroll
        for (int i = 0; i < NC; ++i) {
            const float* r = row + i * HW - w0;   // row start (absolute w indices)
            float4 o;
            o.x = fmaf(wa[0], __ldg(r + ia[0]), wb[0] * __ldg(r + ib[0]));
            o.y = fmaf(wa[1], __ldg(r + ia[1]), wb[1] * __ldg(r + ib[1]));
            o.z = fmaf(wa[2], __ldg(r + ia[2]), wb[2] * __ldg(r + ib[2]));
            o.w = fmaf(wa[3], __ldg(r + ia[3]), wb[3] * __ldg(r + ib[3]));
            *(float4*)(orow + i * HW) = o;
        }
    }
}

extern "C" void kernel_launch(void* const* d_in, const int* in_sizes, int n_in,
                              void* d_out, int out_size)
{
    const float* right_input = (const float*)d_in[0];
    const float* disparity   = (const float*)d_in[1];
    float*       out         = (float*)d_out;

    const int blocks = NTHREADS / THREADS;   // 8192
    spatial_transformer_c4a_kernel<<<blocks, THREADS>>>(right_input, disparity, out);
}

// round 9
// speedup vs baseline: 1.0446x; 1.0446x over previous
#include <cuda_runtime.h>

// SpatialTransformer: 1-D bilinear warp along W.
//
// R6 structure (proven best: no cache hints, 32 regs, occ ~82%): flat
// mapping, 4 channels per thread, coefficients computed once (fb[4]).
//
// R9 changes:
//  1. vn via warp shuffle: lane L's w0+4 element == lane L+1's v.x
//     (consecutive lanes = consecutive w-groups, warps align to rows).
//     Only lane 31 loads a scalar. Removes ~4 LDG.32 per thread.
//  2. Row-end groups (gw=127) join the fast path: floor(w+d)==w still
//     holds there for d in [0,1); vn is never read (no OOB access) and
//     the reference's oob-zeroing is applied as a post-fix on o.w.
//     -> zero fallback for typical data.
//  Fast/slow decision is warp-uniform (__all_sync) so shfl is safe; the
//  general exact-formula fallback still covers arbitrary disparity.

#define ST_B 4
#define ST_C 64
#define ST_H 256
#define ST_W 512

constexpr int HW      = ST_H * ST_W;        // 131072
constexpr int NC      = 4;                  // channels per thread
constexpr int THREADS = 256;
constexpr int NTHREADS = ST_B * (ST_C / NC) * ST_H * (ST_W / 4);  // 2,097,152

__global__ void __launch_bounds__(THREADS)
spatial_transformer_c4w_kernel(const float* __restrict__ in,
                               const float* __restrict__ disp,
                               float* __restrict__ out)
{
    constexpr unsigned FULL = 0xffffffffu;

    const int g  = blockIdx.x * blockDim.x + threadIdx.x;
    const int gw = g & 127;            // w-group (lanes -> consecutive)
    const int h  = (g >> 7) & 255;
    const int cg = (g >> 15) & 15;
    const int b  = g >> 19;
    const int w0 = gw << 2;
    const int lane = threadIdx.x & 31;

    // disparity (b, h, w0..w0+3): 2 MB, L2-hot (16x reuse)
    const float4 d4 = *(const float4*)(disp + ((((b << 8) | h) << 9) | w0));
    const float dv[4] = {d4.x, d4.y, d4.z, d4.w};

    float fb[4];
    bool  fast = true;
    #pragma unroll
    for (int j = 0; j < 4; ++j) {
        float wj = (float)(w0 + j);
        float ry = wj + dv[j];
        float ra = floorf(ry);
        fb[j] = ry - ra;
        fast  = fast && (ra == wj);    // floor lands on own pixel
    }
    const bool edge = (gw == 127);     // last group: w0+4 == W (no vn)
    fast = __all_sync(FULL, fast);     // warp-uniform (shfl safety)

    const int c0   = cg << 2;
    const size_t base = ((size_t)((((b << 6) | c0) << 8) | h) << 9) + w0;
    const float* row  = in  + base;    // points at w0 within the row
    float*       orow = out + base;

    if (fast) {
        float4 v[NC];
        float  vn[NC];
        #pragma unroll
        for (int i = 0; i < NC; ++i)            // front-batched: MLP >= 4
            v[i] = *(const float4*)(row + i * HW);

        if (lane == 31 && !edge) {              // only lane 31 loads vn
            #pragma unroll
            for (int i = 0; i < NC; ++i)
                vn[i] = __ldg(row + i * HW + 4);
        }
        #pragma unroll
        for (int i = 0; i < NC; ++i) {
            float nx = __shfl_down_sync(FULL, v[i].x, 1);  // lane+1's v.x
            if (lane != 31)      vn[i] = nx;
            else if (edge)       vn[i] = 0.0f;  // never a valid read at w=512
        }
        #pragma unroll
        for (int i = 0; i < NC; ++i) {
            float4 o;
            o.x = fmaf(fb[0], v[i].y - v[i].x, v[i].x);
            o.y = fmaf(fb[1], v[i].z - v[i].y, v[i].y);
            o.z = fmaf(fb[2], v[i].w - v[i].z, v[i].z);
            o.w = fmaf(fb[3], vn[i]  - v[i].w, v[i].w);
            // reference semantics at w=511: ry>W-1 -> 0 ; ry==W-1 -> v.w
            if (edge && fb[3] != 0.0f) o.w = 0.0f;
            *(float4*)(orow + i * HW) = o;
        }
    } else {
        // exact reference formula (clamped gather + oob zeroing)
        float wa[4], wb[4];
        int   ia[4], ib[4];
        #pragma unroll
        for (int j = 0; j < 4; ++j) {
            int   w  = w0 + j;
            float ry = (float)w + dv[j];
            float ra = floorf(ry);
            float f  = ry - ra;
            int   a  = (int)ra;
            ia[j] = min(max(a,     0), ST_W - 1);
            ib[j] = min(max(a + 1, 0), ST_W - 1);
            float sc = (ry < 0.0f || ry > (float)(ST_W - 1)) ? 0.0f : 1.0f;
            wa[j] = (1.0f - f) * sc;
            wb[j] = f * sc;
        }
        #pragma unroll
        for (int i = 0; i < NC; ++i) {
            const float* r = row + i * HW - w0;   // row start (absolute w indices)
            float4 o;
            o.x = fmaf(wa[0], __ldg(r + ia[0]), wb[0] * __ldg(r + ib[0]));
            o.y = fmaf(wa[1], __ldg(r + ia[1]), wb[1] * __ldg(r + ib[1]));
            o.z = fmaf(wa[2], __ldg(r + ia[2]), wb[2] * __ldg(r + ib[2]));
            o.w = fmaf(wa[3], __ldg(r + ia[3]), wb[3] * __ldg(r + ib[3]));
            *(float4*)(orow + i * HW) = o;
        }
    }
}

extern "C" void kernel_launch(void* const* d_in, const int* in_sizes, int n_in,
                              void* d_out, int out_size)
{
    const float* right_input = (const float*)d_in[0];
    const float* disparity   = (const float*)d_in[1];
    float*       out         = (float*)d_out;

    const int blocks = NTHREADS / THREADS;   // 8192
    spatial_transformer_c4w_kernel<<<blocks, THREADS>>>(right_input, disparity, out);
}